// round 7
// baseline (speedup 1.0000x reference)
#include <cuda_runtime.h>
#include <cuda_fp16.h>

// Problem constants: N=100000, E=3200000, FEAT=128, HID=32, EMB=16
#define NMAX 100000
#define EMAX 3200000
#define SCAN_B 1024
#define NBLK ((NMAX + SCAN_B - 1) / SCAN_B)   // 98

// ---- scratch (device globals) ----
__device__ __half g_h1h[NMAX * 32];
__device__ float  g_hp1[NMAX * 32];
__device__ float  g_als1[NMAX], g_ald1[NMAX];
__device__ __half g_h2h[NMAX * 16];
__device__ float  g_als2[NMAX], g_ald2[NMAX];

__device__ int g_deg [NMAX];
__device__ int g_scan[NMAX];
__device__ int g_off [NMAX];
__device__ int g_pos [NMAX];
__device__ int g_bsum [NBLK];
__device__ int g_bsumx[NBLK];
__device__ int g_cnt;                 // last-block-done counter (memset to 0 per launch)
__device__ int g_esrc[EMAX];

__device__ __forceinline__ float leaky(float a) { return a > 0.0f ? a : 0.2f * a; }

// ---- packed f32x2 helpers ----
__device__ __forceinline__ unsigned long long pack2(float a, float b) {
    unsigned long long r;
    asm("mov.b64 %0, {%1, %2};" : "=l"(r) : "r"(__float_as_int(a)), "r"(__float_as_int(b)));
    return r;
}
__device__ __forceinline__ unsigned long long fma2(unsigned long long a, unsigned long long b, unsigned long long c) {
    unsigned long long d;
    asm("fma.rn.f32x2 %0, %1, %2, %3;" : "=l"(d) : "l"(a), "l"(b), "l"(c));
    return d;
}
__device__ __forceinline__ float2 unpack2(unsigned long long v) {
    int lo, hi;
    asm("mov.b64 {%0, %1}, %2;" : "=r"(lo), "=r"(hi) : "l"(v));
    return make_float2(__int_as_float(lo), __int_as_float(hi));
}

// ===========================================================================
// CSR build
// ===========================================================================
__global__ __launch_bounds__(256) void hist_kernel(const int* __restrict__ dst, int E) {
    int t = blockIdx.x * 256 + threadIdx.x;
    int e = t * 4;
    if (e + 3 < E) {
        int4 d = *reinterpret_cast<const int4*>(dst + e);
        atomicAdd(&g_deg[d.x], 1);
        atomicAdd(&g_deg[d.y], 1);
        atomicAdd(&g_deg[d.z], 1);
        atomicAdd(&g_deg[d.w], 1);
    } else {
        for (; e < E; e++) atomicAdd(&g_deg[__ldg(dst + e)], 1);
    }
}

// scan1: per-block inclusive scan + block sums; LAST block to finish also
// performs the exclusive scan of the block sums (replaces scan2).
__global__ __launch_bounds__(SCAN_B) void scan1_kernel(int N, int nb) {
    __shared__ int sh[SCAN_B];
    int gid = blockIdx.x * SCAN_B + threadIdx.x;
    int v = (gid < N) ? g_deg[gid] : 0;
    sh[threadIdx.x] = v;
    __syncthreads();
#pragma unroll
    for (int o = 1; o < SCAN_B; o <<= 1) {
        int t = (threadIdx.x >= o) ? sh[threadIdx.x - o] : 0;
        __syncthreads();
        sh[threadIdx.x] += t;
        __syncthreads();
    }
    if (gid < N) g_scan[gid] = sh[threadIdx.x];
    __shared__ int s_last;
    if (threadIdx.x == SCAN_B - 1) {
        g_bsum[blockIdx.x] = sh[SCAN_B - 1];
        __threadfence();
        s_last = (atomicAdd(&g_cnt, 1) == nb - 1);
    }
    __syncthreads();
    if (s_last) {
        // this is the last block to finish: scan the block sums (nb <= 128)
        __shared__ int sb[128];
        int t = threadIdx.x;
        if (t < 128) {
            int bv = (t < nb) ? g_bsum[t] : 0;
            sb[t] = bv;
            __syncthreads();
#pragma unroll
            for (int o = 1; o < 128; o <<= 1) {
                int u = (t >= o) ? sb[t - o] : 0;
                __syncthreads();
                sb[t] += u;
                __syncthreads();
            }
            if (t < nb) g_bsumx[t] = sb[t] - bv;
        }
    }
}

__global__ __launch_bounds__(256) void scan3_kernel(int N) {
    int gid = blockIdx.x * 256 + threadIdx.x;
    if (gid < N) {
        int off = g_scan[gid] - g_deg[gid] + g_bsumx[gid / SCAN_B];
        g_off[gid] = off;
        g_pos[gid] = off;
    }
}

__global__ __launch_bounds__(256) void permute_kernel(
    const int* __restrict__ src, const int* __restrict__ dst, int E)
{
    int e = blockIdx.x * 256 + threadIdx.x;
    if (e >= E) return;
    int d = __ldg(dst + e);
    int p = atomicAdd(&g_pos[d], 1);
    g_esrc[p] = __ldg(src + e);
}

// ===========================================================================
// node1: h1 = x @ W1 (-> fp16) via packed f32x2 FFMA2; two nodes per thread.
// ===========================================================================
__global__ __launch_bounds__(256) void node1_kernel(
    const float* __restrict__ x, const float* __restrict__ W1,
    const float* __restrict__ asrc, const float* __restrict__ adst, int N)
{
    __shared__ __align__(16) unsigned long long Wp[128 * 16];  // W1 rows as f32 pairs
    __shared__ float s_as[32], s_ad[32];
    for (int i = threadIdx.x; i < 128 * 16; i += 256) {
        float2 w = reinterpret_cast<const float2*>(W1)[i];
        Wp[i] = pack2(w.x, w.y);
    }
    if (threadIdx.x < 32) { s_as[threadIdx.x] = asrc[threadIdx.x]; s_ad[threadIdx.x] = adst[threadIdx.x]; }
    __syncthreads();

    int n0 = blockIdx.x * 512 + threadIdx.x;
    int n1 = n0 + 256;
    if (n0 >= N) return;
    bool v1 = (n1 < N);
    int n1c = v1 ? n1 : n0;

    unsigned long long a0[16], a1[16];
#pragma unroll
    for (int i = 0; i < 16; i++) { a0[i] = 0ull; a1[i] = 0ull; }

    const float4* xr0 = reinterpret_cast<const float4*>(x + (size_t)n0  * 128);
    const float4* xr1 = reinterpret_cast<const float4*>(x + (size_t)n1c * 128);
#pragma unroll 2
    for (int k4 = 0; k4 < 32; k4++) {
        float4 xv0 = __ldg(&xr0[k4]);
        float4 xv1 = __ldg(&xr1[k4]);
        float xk0[4] = {xv0.x, xv0.y, xv0.z, xv0.w};
        float xk1[4] = {xv1.x, xv1.y, xv1.z, xv1.w};
#pragma unroll
        for (int kk = 0; kk < 4; kk++) {
            int k = k4 * 4 + kk;
            unsigned long long x0p = pack2(xk0[kk], xk0[kk]);
            unsigned long long x1p = pack2(xk1[kk], xk1[kk]);
            const ulonglong2* wr = reinterpret_cast<const ulonglong2*>(&Wp[k * 16]);
#pragma unroll
            for (int c = 0; c < 8; c++) {
                ulonglong2 wp = wr[c];
                a0[c * 2]     = fma2(x0p, wp.x, a0[c * 2]);
                a0[c * 2 + 1] = fma2(x0p, wp.y, a0[c * 2 + 1]);
                a1[c * 2]     = fma2(x1p, wp.x, a1[c * 2]);
                a1[c * 2 + 1] = fma2(x1p, wp.y, a1[c * 2 + 1]);
            }
        }
    }

    float als0 = 0.f, ald0 = 0.f, als1v = 0.f, ald1v = 0.f;
    __half2* hp0 = reinterpret_cast<__half2*>(&g_h1h[n0 * 32]);
    __half2* hp1 = reinterpret_cast<__half2*>(&g_h1h[n1c * 32]);
#pragma unroll
    for (int i = 0; i < 16; i++) {
        float2 f0 = unpack2(a0[i]);
        float2 f1 = unpack2(a1[i]);
        float sa0 = s_as[i * 2], sa1 = s_as[i * 2 + 1];
        float da0 = s_ad[i * 2], da1 = s_ad[i * 2 + 1];
        als0  += f0.x * sa0 + f0.y * sa1;
        ald0  += f0.x * da0 + f0.y * da1;
        als1v += f1.x * sa0 + f1.y * sa1;
        ald1v += f1.x * da0 + f1.y * da1;
        hp0[i] = __floats2half2_rn(f0.x, f0.y);
        if (v1) hp1[i] = __floats2half2_rn(f1.x, f1.y);
    }
    g_als1[n0] = als0; g_ald1[n0] = ald0;
    if (v1) { g_als1[n1] = als1v; g_ald1[n1] = ald1v; }
}

// ===========================================================================
// agg1: layer-1 aggregate. TWO nodes per warp, 16 lanes each, pipelined.
// ===========================================================================
__global__ __launch_bounds__(256) void agg1_kernel(const float* __restrict__ b1, int N)
{
    int wid = (blockIdx.x * 256 + threadIdx.x) >> 5;
    int lane = threadIdx.x & 31;
    int half = lane >> 4;
    int l16 = lane & 15;
    int n = wid * 2 + half;
    if (wid * 2 >= N) return;
    bool nvalid = (n < N);
    int nn = nvalid ? n : (N - 1);

    float ald = __ldg(&g_ald1[nn]);
    int start = g_off[nn];
    int deg = g_deg[nn];
    int end = start + deg;

    int nb = (deg + 15) >> 4;
    { int t = __shfl_xor_sync(0xffffffffu, nb, 16); nb = nb > t ? nb : t; }

    int s = 0; float w;
    {
        int idx = start + l16;
        bool v = nvalid && idx < end;
        float al = 0.f;
        if (v) { s = __ldg(&g_esrc[idx]); al = __ldg(&g_als1[s]); }
        w = v ? __expf(leaky(al + ald)) : 0.f;
    }

    float2 a0 = make_float2(0.f,0.f), a1 = make_float2(0.f,0.f);
    float2 a2 = make_float2(0.f,0.f), a3 = make_float2(0.f,0.f);
    float den = 0.f;
    const __half2* h1p = reinterpret_cast<const __half2*>(g_h1h);
    for (int b = 0; b < nb; b++) {
        int idx2 = start + (b + 1) * 16 + l16;
        bool v2 = nvalid && idx2 < end;
        int s2 = 0; float al2 = 0.f;
        if (v2) { s2 = __ldg(&g_esrc[idx2]); al2 = __ldg(&g_als1[s2]); }

        den += w;
#pragma unroll
        for (int j = 0; j < 16; j += 4) {
            int   s0 = __shfl_sync(0xffffffffu, s, j,     16);
            int   s1 = __shfl_sync(0xffffffffu, s, j + 1, 16);
            int   s2b= __shfl_sync(0xffffffffu, s, j + 2, 16);
            int   s3 = __shfl_sync(0xffffffffu, s, j + 3, 16);
            float w0 = __shfl_sync(0xffffffffu, w, j,     16);
            float w1 = __shfl_sync(0xffffffffu, w, j + 1, 16);
            float w2 = __shfl_sync(0xffffffffu, w, j + 2, 16);
            float w3 = __shfl_sync(0xffffffffu, w, j + 3, 16);
            float2 f0 = __half22float2(__ldg(&h1p[s0 * 16 + l16]));
            float2 f1 = __half22float2(__ldg(&h1p[s1 * 16 + l16]));
            float2 f2 = __half22float2(__ldg(&h1p[s2b* 16 + l16]));
            float2 f3 = __half22float2(__ldg(&h1p[s3 * 16 + l16]));
            a0.x = fmaf(w0, f0.x, a0.x); a0.y = fmaf(w0, f0.y, a0.y);
            a1.x = fmaf(w1, f1.x, a1.x); a1.y = fmaf(w1, f1.y, a1.y);
            a2.x = fmaf(w2, f2.x, a2.x); a2.y = fmaf(w2, f2.y, a2.y);
            a3.x = fmaf(w3, f3.x, a3.x); a3.y = fmaf(w3, f3.y, a3.y);
        }
        s = s2;
        w = v2 ? __expf(leaky(al2 + ald)) : 0.f;
    }
    float2 acc = make_float2((a0.x + a1.x) + (a2.x + a3.x), (a0.y + a1.y) + (a2.y + a3.y));
#pragma unroll
    for (int o = 8; o; o >>= 1) den += __shfl_xor_sync(0xffffffffu, den, o, 16);

    float wself = __expf(leaky(__ldg(&g_als1[nn]) + ald));
    den += wself;
    float2 hs = __half22float2(__ldg(&h1p[nn * 16 + l16]));
    acc.x = fmaf(wself, hs.x, acc.x);
    acc.y = fmaf(wself, hs.y, acc.y);

    float inv = 1.0f / (den + 1e-16f);
    if (nvalid) {
        float2 bv = __ldg(&reinterpret_cast<const float2*>(b1)[l16]);
        float2 r;
        r.x = fmaxf(fmaf(acc.x, inv, bv.x), 0.f);
        r.y = fmaxf(fmaf(acc.y, inv, bv.y), 0.f);
        reinterpret_cast<float2*>(&g_hp1[n * 32])[l16] = r;
    }
}

// ===========================================================================
// node2: h2 = h' @ W2 (-> fp16); al_s2/al_d2
// ===========================================================================
__global__ __launch_bounds__(256) void node2_kernel(
    const float* __restrict__ W2,
    const float* __restrict__ asrc, const float* __restrict__ adst, int N)
{
    __shared__ float Ws[32 * 16];
    __shared__ float s_as[16], s_ad[16];
    for (int i = threadIdx.x; i < 32 * 16; i += 256) Ws[i] = W2[i];
    if (threadIdx.x < 16) { s_as[threadIdx.x] = asrc[threadIdx.x]; s_ad[threadIdx.x] = adst[threadIdx.x]; }
    __syncthreads();

    int n = blockIdx.x * 256 + threadIdx.x;
    if (n >= N) return;

    float4 h2[4];
#pragma unroll
    for (int i = 0; i < 4; i++) h2[i] = make_float4(0.f, 0.f, 0.f, 0.f);

    const float4* hp = reinterpret_cast<const float4*>(&g_hp1[n * 32]);
#pragma unroll
    for (int c4 = 0; c4 < 8; c4++) {
        float4 xv = hp[c4];
        float xk[4] = {xv.x, xv.y, xv.z, xv.w};
#pragma unroll
        for (int kk = 0; kk < 4; kk++) {
            const float4* wr = reinterpret_cast<const float4*>(&Ws[(c4 * 4 + kk) * 16]);
            float xs = xk[kk];
#pragma unroll
            for (int o4 = 0; o4 < 4; o4++) {
                float4 w = wr[o4];
                h2[o4].x = fmaf(xs, w.x, h2[o4].x); h2[o4].y = fmaf(xs, w.y, h2[o4].y);
                h2[o4].z = fmaf(xs, w.z, h2[o4].z); h2[o4].w = fmaf(xs, w.w, h2[o4].w);
            }
        }
    }

    float als = 0.f, ald = 0.f;
#pragma unroll
    for (int o4 = 0; o4 < 4; o4++) {
        float4 a  = h2[o4];
        float4 s4 = reinterpret_cast<const float4*>(s_as)[o4];
        float4 d4 = reinterpret_cast<const float4*>(s_ad)[o4];
        als += a.x*s4.x + a.y*s4.y + a.z*s4.z + a.w*s4.w;
        ald += a.x*d4.x + a.y*d4.y + a.z*d4.z + a.w*d4.w;
    }
    g_als2[n] = als; g_ald2[n] = ald;

    __half2* out = reinterpret_cast<__half2*>(&g_h2h[n * 16]);
#pragma unroll
    for (int o4 = 0; o4 < 4; o4++) {
        out[o4 * 2]     = __floats2half2_rn(h2[o4].x, h2[o4].y);
        out[o4 * 2 + 1] = __floats2half2_rn(h2[o4].z, h2[o4].w);
    }
}

// ===========================================================================
// agg2: layer-2 aggregate + output. FOUR nodes per warp, 8 lanes each,
// pipelined like agg1.
// ===========================================================================
__global__ __launch_bounds__(256) void agg2_kernel(
    const float* __restrict__ b2, float* __restrict__ out, int N)
{
    int wid = (blockIdx.x * 256 + threadIdx.x) >> 5;
    int lane = threadIdx.x & 31;
    int quad = lane >> 3;
    int l8 = lane & 7;
    int n = wid * 4 + quad;
    if (wid * 4 >= N) return;
    bool nvalid = (n < N);
    int nn = nvalid ? n : (N - 1);

    float ald = __ldg(&g_ald2[nn]);
    int start = g_off[nn];
    int deg = g_deg[nn];
    int end = start + deg;

    int nb = (deg + 7) >> 3;
    { int t = __shfl_xor_sync(0xffffffffu, nb, 8);  nb = nb > t ? nb : t; }
    { int t = __shfl_xor_sync(0xffffffffu, nb, 16); nb = nb > t ? nb : t; }

    int s = 0; float w;
    {
        int idx = start + l8;
        bool v = nvalid && idx < end;
        float al = 0.f;
        if (v) { s = __ldg(&g_esrc[idx]); al = __ldg(&g_als2[s]); }
        w = v ? __expf(leaky(al + ald)) : 0.f;
    }

    float2 a0 = make_float2(0.f,0.f), a1 = make_float2(0.f,0.f);
    float2 a2 = make_float2(0.f,0.f), a3 = make_float2(0.f,0.f);
    float den = 0.f;
    const __half2* h2p = reinterpret_cast<const __half2*>(g_h2h);
    for (int b = 0; b < nb; b++) {
        int idx2 = start + (b + 1) * 8 + l8;
        bool v2 = nvalid && idx2 < end;
        int s2 = 0; float al2 = 0.f;
        if (v2) { s2 = __ldg(&g_esrc[idx2]); al2 = __ldg(&g_als2[s2]); }

        den += w;
#pragma unroll
        for (int j = 0; j < 8; j += 4) {
            int   s0 = __shfl_sync(0xffffffffu, s, j,     8);
            int   s1 = __shfl_sync(0xffffffffu, s, j + 1, 8);
            int   s2b= __shfl_sync(0xffffffffu, s, j + 2, 8);
            int   s3 = __shfl_sync(0xffffffffu, s, j + 3, 8);
            float w0 = __shfl_sync(0xffffffffu, w, j,     8);
            float w1 = __shfl_sync(0xffffffffu, w, j + 1, 8);
            float w2 = __shfl_sync(0xffffffffu, w, j + 2, 8);
            float w3 = __shfl_sync(0xffffffffu, w, j + 3, 8);
            float2 f0 = __half22float2(__ldg(&h2p[s0 * 8 + l8]));
            float2 f1 = __half22float2(__ldg(&h2p[s1 * 8 + l8]));
            float2 f2 = __half22float2(__ldg(&h2p[s2b* 8 + l8]));
            float2 f3 = __half22float2(__ldg(&h2p[s3 * 8 + l8]));
            a0.x = fmaf(w0, f0.x, a0.x); a0.y = fmaf(w0, f0.y, a0.y);
            a1.x = fmaf(w1, f1.x, a1.x); a1.y = fmaf(w1, f1.y, a1.y);
            a2.x = fmaf(w2, f2.x, a2.x); a2.y = fmaf(w2, f2.y, a2.y);
            a3.x = fmaf(w3, f3.x, a3.x); a3.y = fmaf(w3, f3.y, a3.y);
        }
        s = s2;
        w = v2 ? __expf(leaky(al2 + ald)) : 0.f;
    }
    float2 acc = make_float2((a0.x + a1.x) + (a2.x + a3.x), (a0.y + a1.y) + (a2.y + a3.y));
#pragma unroll
    for (int o = 4; o; o >>= 1) den += __shfl_xor_sync(0xffffffffu, den, o, 8);

    float wself = __expf(leaky(__ldg(&g_als2[nn]) + ald));
    den += wself;
    float2 hs = __half22float2(__ldg(&h2p[nn * 8 + l8]));
    acc.x = fmaf(wself, hs.x, acc.x);
    acc.y = fmaf(wself, hs.y, acc.y);

    float inv = 1.0f / (den + 1e-16f);
    if (nvalid) {
        float2 bv = __ldg(&reinterpret_cast<const float2*>(b2)[l8]);
        float2 r;
        r.x = fmaf(acc.x, inv, bv.x);
        r.y = fmaf(acc.y, inv, bv.y);
        reinterpret_cast<float2*>(&out[n * 16])[l8] = r;
    }
}

// ===========================================================================
extern "C" void kernel_launch(void* const* d_in, const int* in_sizes, int n_in,
                              void* d_out, int out_size)
{
    const float* x   = (const float*)d_in[0];
    const int*   ei  = (const int*)  d_in[1];
    const float* W1  = (const float*)d_in[3];
    const float* as1 = (const float*)d_in[4];
    const float* ad1 = (const float*)d_in[5];
    const float* b1  = (const float*)d_in[6];
    const float* W2  = (const float*)d_in[7];
    const float* as2 = (const float*)d_in[8];
    const float* ad2 = (const float*)d_in[9];
    const float* b2  = (const float*)d_in[10];

    int N = in_sizes[0] / 128;
    int E = in_sizes[1] / 2;
    const int* src = ei;
    const int* dst = ei + E;

    void* p_deg = nullptr; cudaGetSymbolAddress(&p_deg, g_deg);
    void* p_cnt = nullptr; cudaGetSymbolAddress(&p_cnt, g_cnt);
    cudaMemsetAsync(p_deg, 0, (size_t)N * sizeof(int));
    cudaMemsetAsync(p_cnt, 0, sizeof(int));

    int nblkN = (N + 255) / 256;
    int nblkE = (E + 255) / 256;
    int nscan = (N + SCAN_B - 1) / SCAN_B;

    hist_kernel <<<(E / 4 + 256) / 256, 256>>>(dst, E);
    scan1_kernel<<<nscan, SCAN_B>>>(N, nscan);
    scan3_kernel<<<nblkN, 256>>>(N);
    permute_kernel<<<nblkE, 256>>>(src, dst, E);

    node1_kernel<<<(N + 511) / 512, 256>>>(x, W1, as1, ad1, N);
    int nwarp1 = (((N + 1) / 2) * 32 + 255) / 256;
    agg1_kernel<<<nwarp1, 256>>>(b1, N);

    node2_kernel<<<nblkN, 256>>>(W2, as2, ad2, N);
    int nwarp2 = (((N + 3) / 4) * 32 + 255) / 256;
    agg2_kernel<<<nwarp2, 256>>>(b2, (float*)d_out, N);
}

// round 8
// speedup vs baseline: 1.0297x; 1.0297x over previous
#include <cuda_runtime.h>
#include <cuda_fp16.h>

// Problem constants: N=100000, E=3200000, FEAT=128, HID=32, EMB=16
#define NMAX 100000
#define EMAX 3200000
#define SCAN_B 1024
#define NBLK ((NMAX + SCAN_B - 1) / SCAN_B)   // 98

// ---- scratch (device globals) ----
__device__ __half g_h1h[NMAX * 32];
__device__ float  g_hp1[NMAX * 32];
__device__ float  g_als1[NMAX], g_ald1[NMAX];
__device__ __half g_h2h[NMAX * 16];
__device__ float  g_als2[NMAX], g_ald2[NMAX];

__device__ int g_deg [NMAX];
__device__ int g_scan[NMAX];
__device__ int g_off [NMAX];
__device__ int g_bsum [NBLK];
__device__ int g_bsumx[NBLK];
__device__ int g_cnt;
__device__ int g_rank[EMAX];          // per-edge rank within its dst group
__device__ int g_esrc[EMAX];

__device__ __forceinline__ float leaky(float a) { return a > 0.0f ? a : 0.2f * a; }

// ===========================================================================
// Fused hist + node1. Blocks [0, histB): degree histogram, capturing each
// edge's rank (atomicAdd return). Blocks [histB, ...): node1 GEMM (fp32,
// one node per thread, low regs). Independent work: atomics overlap FMA.
// ===========================================================================
__global__ __launch_bounds__(256) void hist_node1_kernel(
    const int* __restrict__ dst, int E,
    const float* __restrict__ x, const float* __restrict__ W1,
    const float* __restrict__ asrc, const float* __restrict__ adst, int N, int histB)
{
    if ((int)blockIdx.x < histB) {
        int t = blockIdx.x * 256 + threadIdx.x;
        int e = t * 4;
        if (e + 3 < E) {
            int4 d = *reinterpret_cast<const int4*>(dst + e);
            int4 r;
            r.x = atomicAdd(&g_deg[d.x], 1);
            r.y = atomicAdd(&g_deg[d.y], 1);
            r.z = atomicAdd(&g_deg[d.z], 1);
            r.w = atomicAdd(&g_deg[d.w], 1);
            *reinterpret_cast<int4*>(g_rank + e) = r;
        } else {
            for (; e < E; e++) g_rank[e] = atomicAdd(&g_deg[__ldg(dst + e)], 1);
        }
        return;
    }

    // ---- node1: h1 = x @ W1 (-> fp16); al_s1/al_d1 ----
    __shared__ float Ws[128 * 32];
    __shared__ float s_as[32], s_ad[32];
    for (int i = threadIdx.x; i < 128 * 32; i += 256) Ws[i] = W1[i];
    if (threadIdx.x < 32) { s_as[threadIdx.x] = asrc[threadIdx.x]; s_ad[threadIdx.x] = adst[threadIdx.x]; }
    __syncthreads();

    int n = (blockIdx.x - histB) * 256 + threadIdx.x;
    if (n >= N) return;

    float4 acc[8];
#pragma unroll
    for (int i = 0; i < 8; i++) acc[i] = make_float4(0.f, 0.f, 0.f, 0.f);

    const float4* xr = reinterpret_cast<const float4*>(x + (size_t)n * 128);
#pragma unroll 4
    for (int k4 = 0; k4 < 32; k4++) {
        float4 xv = __ldg(&xr[k4]);
        float xk[4] = {xv.x, xv.y, xv.z, xv.w};
#pragma unroll
        for (int kk = 0; kk < 4; kk++) {
            const float4* wr = reinterpret_cast<const float4*>(&Ws[(k4 * 4 + kk) * 32]);
            float xs = xk[kk];
#pragma unroll
            for (int c4 = 0; c4 < 8; c4++) {
                float4 w = wr[c4];
                acc[c4].x = fmaf(xs, w.x, acc[c4].x); acc[c4].y = fmaf(xs, w.y, acc[c4].y);
                acc[c4].z = fmaf(xs, w.z, acc[c4].z); acc[c4].w = fmaf(xs, w.w, acc[c4].w);
            }
        }
    }

    float als = 0.f, ald = 0.f;
#pragma unroll
    for (int c4 = 0; c4 < 8; c4++) {
        float4 a  = acc[c4];
        float4 s4 = reinterpret_cast<const float4*>(s_as)[c4];
        float4 d4 = reinterpret_cast<const float4*>(s_ad)[c4];
        als += a.x*s4.x + a.y*s4.y + a.z*s4.z + a.w*s4.w;
        ald += a.x*d4.x + a.y*d4.y + a.z*d4.z + a.w*d4.w;
    }
    g_als1[n] = als; g_ald1[n] = ald;

    __half2* hp = reinterpret_cast<__half2*>(&g_h1h[n * 32]);
#pragma unroll
    for (int c4 = 0; c4 < 8; c4++) {
        hp[c4 * 2]     = __floats2half2_rn(acc[c4].x, acc[c4].y);
        hp[c4 * 2 + 1] = __floats2half2_rn(acc[c4].z, acc[c4].w);
    }
}

// ===========================================================================
// scan1: per-block inclusive scan + block sums; last block also scans sums.
// ===========================================================================
__global__ __launch_bounds__(SCAN_B) void scan1_kernel(int N, int nb) {
    __shared__ int sh[SCAN_B];
    int gid = blockIdx.x * SCAN_B + threadIdx.x;
    int v = (gid < N) ? g_deg[gid] : 0;
    sh[threadIdx.x] = v;
    __syncthreads();
#pragma unroll
    for (int o = 1; o < SCAN_B; o <<= 1) {
        int t = (threadIdx.x >= o) ? sh[threadIdx.x - o] : 0;
        __syncthreads();
        sh[threadIdx.x] += t;
        __syncthreads();
    }
    if (gid < N) g_scan[gid] = sh[threadIdx.x];
    __shared__ int s_last;
    if (threadIdx.x == SCAN_B - 1) {
        g_bsum[blockIdx.x] = sh[SCAN_B - 1];
        __threadfence();
        s_last = (atomicAdd(&g_cnt, 1) == nb - 1);
    }
    __syncthreads();
    if (s_last) {
        __shared__ int sb[128];
        int t = threadIdx.x;
        if (t < 128) {
            int bv = (t < nb) ? g_bsum[t] : 0;
            sb[t] = bv;
            __syncthreads();
#pragma unroll
            for (int o = 1; o < 128; o <<= 1) {
                int u = (t >= o) ? sb[t - o] : 0;
                __syncthreads();
                sb[t] += u;
                __syncthreads();
            }
            if (t < nb) g_bsumx[t] = sb[t] - bv;
        }
    }
}

__global__ __launch_bounds__(256) void scan3_kernel(int N) {
    int gid = blockIdx.x * 256 + threadIdx.x;
    if (gid < N)
        g_off[gid] = g_scan[gid] - g_deg[gid] + g_bsumx[gid / SCAN_B];
}

// ===========================================================================
// permute: atomic-free. p = off[dst[e]] + rank[e]; esrc[p] = src[e].
// ===========================================================================
__global__ __launch_bounds__(256) void permute_kernel(
    const int* __restrict__ src, const int* __restrict__ dst, int E)
{
    int t = blockIdx.x * 256 + threadIdx.x;
    int e = t * 4;
    if (e + 3 < E) {
        int4 d = *reinterpret_cast<const int4*>(dst + e);
        int4 r = *reinterpret_cast<const int4*>(g_rank + e);
        int4 s = *reinterpret_cast<const int4*>(src + e);
        int p0 = __ldg(&g_off[d.x]) + r.x;
        int p1 = __ldg(&g_off[d.y]) + r.y;
        int p2 = __ldg(&g_off[d.z]) + r.z;
        int p3 = __ldg(&g_off[d.w]) + r.w;
        g_esrc[p0] = s.x;
        g_esrc[p1] = s.y;
        g_esrc[p2] = s.z;
        g_esrc[p3] = s.w;
    } else {
        for (; e < E; e++) {
            int d = __ldg(dst + e);
            g_esrc[__ldg(&g_off[d]) + g_rank[e]] = __ldg(src + e);
        }
    }
}

// ===========================================================================
// agg1: layer-1 aggregate. TWO nodes per warp, 16 lanes each, pipelined.
// ===========================================================================
__global__ __launch_bounds__(256) void agg1_kernel(const float* __restrict__ b1, int N)
{
    int wid = (blockIdx.x * 256 + threadIdx.x) >> 5;
    int lane = threadIdx.x & 31;
    int half = lane >> 4;
    int l16 = lane & 15;
    int n = wid * 2 + half;
    if (wid * 2 >= N) return;
    bool nvalid = (n < N);
    int nn = nvalid ? n : (N - 1);

    float ald = __ldg(&g_ald1[nn]);
    int start = g_off[nn];
    int deg = g_deg[nn];
    int end = start + deg;

    int nb = (deg + 15) >> 4;
    { int t = __shfl_xor_sync(0xffffffffu, nb, 16); nb = nb > t ? nb : t; }

    int s = 0; float w;
    {
        int idx = start + l16;
        bool v = nvalid && idx < end;
        float al = 0.f;
        if (v) { s = __ldg(&g_esrc[idx]); al = __ldg(&g_als1[s]); }
        w = v ? __expf(leaky(al + ald)) : 0.f;
    }

    float2 a0 = make_float2(0.f,0.f), a1 = make_float2(0.f,0.f);
    float2 a2 = make_float2(0.f,0.f), a3 = make_float2(0.f,0.f);
    float den = 0.f;
    const __half2* h1p = reinterpret_cast<const __half2*>(g_h1h);
    for (int b = 0; b < nb; b++) {
        int idx2 = start + (b + 1) * 16 + l16;
        bool v2 = nvalid && idx2 < end;
        int s2 = 0; float al2 = 0.f;
        if (v2) { s2 = __ldg(&g_esrc[idx2]); al2 = __ldg(&g_als1[s2]); }

        den += w;
#pragma unroll
        for (int j = 0; j < 16; j += 4) {
            int   s0 = __shfl_sync(0xffffffffu, s, j,     16);
            int   s1 = __shfl_sync(0xffffffffu, s, j + 1, 16);
            int   s2b= __shfl_sync(0xffffffffu, s, j + 2, 16);
            int   s3 = __shfl_sync(0xffffffffu, s, j + 3, 16);
            float w0 = __shfl_sync(0xffffffffu, w, j,     16);
            float w1 = __shfl_sync(0xffffffffu, w, j + 1, 16);
            float w2 = __shfl_sync(0xffffffffu, w, j + 2, 16);
            float w3 = __shfl_sync(0xffffffffu, w, j + 3, 16);
            float2 f0 = __half22float2(__ldg(&h1p[s0 * 16 + l16]));
            float2 f1 = __half22float2(__ldg(&h1p[s1 * 16 + l16]));
            float2 f2 = __half22float2(__ldg(&h1p[s2b* 16 + l16]));
            float2 f3 = __half22float2(__ldg(&h1p[s3 * 16 + l16]));
            a0.x = fmaf(w0, f0.x, a0.x); a0.y = fmaf(w0, f0.y, a0.y);
            a1.x = fmaf(w1, f1.x, a1.x); a1.y = fmaf(w1, f1.y, a1.y);
            a2.x = fmaf(w2, f2.x, a2.x); a2.y = fmaf(w2, f2.y, a2.y);
            a3.x = fmaf(w3, f3.x, a3.x); a3.y = fmaf(w3, f3.y, a3.y);
        }
        s = s2;
        w = v2 ? __expf(leaky(al2 + ald)) : 0.f;
    }
    float2 acc = make_float2((a0.x + a1.x) + (a2.x + a3.x), (a0.y + a1.y) + (a2.y + a3.y));
#pragma unroll
    for (int o = 8; o; o >>= 1) den += __shfl_xor_sync(0xffffffffu, den, o, 16);

    float wself = __expf(leaky(__ldg(&g_als1[nn]) + ald));
    den += wself;
    float2 hs = __half22float2(__ldg(&h1p[nn * 16 + l16]));
    acc.x = fmaf(wself, hs.x, acc.x);
    acc.y = fmaf(wself, hs.y, acc.y);

    float inv = 1.0f / (den + 1e-16f);
    if (nvalid) {
        float2 bv = __ldg(&reinterpret_cast<const float2*>(b1)[l16]);
        float2 r;
        r.x = fmaxf(fmaf(acc.x, inv, bv.x), 0.f);
        r.y = fmaxf(fmaf(acc.y, inv, bv.y), 0.f);
        reinterpret_cast<float2*>(&g_hp1[n * 32])[l16] = r;
    }
}

// ===========================================================================
// node2: h2 = h' @ W2 (-> fp16); al_s2/al_d2
// ===========================================================================
__global__ __launch_bounds__(256) void node2_kernel(
    const float* __restrict__ W2,
    const float* __restrict__ asrc, const float* __restrict__ adst, int N)
{
    __shared__ float Ws[32 * 16];
    __shared__ float s_as[16], s_ad[16];
    for (int i = threadIdx.x; i < 32 * 16; i += 256) Ws[i] = W2[i];
    if (threadIdx.x < 16) { s_as[threadIdx.x] = asrc[threadIdx.x]; s_ad[threadIdx.x] = adst[threadIdx.x]; }
    __syncthreads();

    int n = blockIdx.x * 256 + threadIdx.x;
    if (n >= N) return;

    float4 h2[4];
#pragma unroll
    for (int i = 0; i < 4; i++) h2[i] = make_float4(0.f, 0.f, 0.f, 0.f);

    const float4* hp = reinterpret_cast<const float4*>(&g_hp1[n * 32]);
#pragma unroll
    for (int c4 = 0; c4 < 8; c4++) {
        float4 xv = hp[c4];
        float xk[4] = {xv.x, xv.y, xv.z, xv.w};
#pragma unroll
        for (int kk = 0; kk < 4; kk++) {
            const float4* wr = reinterpret_cast<const float4*>(&Ws[(c4 * 4 + kk) * 16]);
            float xs = xk[kk];
#pragma unroll
            for (int o4 = 0; o4 < 4; o4++) {
                float4 w = wr[o4];
                h2[o4].x = fmaf(xs, w.x, h2[o4].x); h2[o4].y = fmaf(xs, w.y, h2[o4].y);
                h2[o4].z = fmaf(xs, w.z, h2[o4].z); h2[o4].w = fmaf(xs, w.w, h2[o4].w);
            }
        }
    }

    float als = 0.f, ald = 0.f;
#pragma unroll
    for (int o4 = 0; o4 < 4; o4++) {
        float4 a  = h2[o4];
        float4 s4 = reinterpret_cast<const float4*>(s_as)[o4];
        float4 d4 = reinterpret_cast<const float4*>(s_ad)[o4];
        als += a.x*s4.x + a.y*s4.y + a.z*s4.z + a.w*s4.w;
        ald += a.x*d4.x + a.y*d4.y + a.z*d4.z + a.w*d4.w;
    }
    g_als2[n] = als; g_ald2[n] = ald;

    __half2* out = reinterpret_cast<__half2*>(&g_h2h[n * 16]);
#pragma unroll
    for (int o4 = 0; o4 < 4; o4++) {
        out[o4 * 2]     = __floats2half2_rn(h2[o4].x, h2[o4].y);
        out[o4 * 2 + 1] = __floats2half2_rn(h2[o4].z, h2[o4].w);
    }
}

// ===========================================================================
// agg2: layer-2 aggregate + output. FOUR nodes per warp, 8 lanes, pipelined.
// ===========================================================================
__global__ __launch_bounds__(256) void agg2_kernel(
    const float* __restrict__ b2, float* __restrict__ out, int N)
{
    int wid = (blockIdx.x * 256 + threadIdx.x) >> 5;
    int lane = threadIdx.x & 31;
    int quad = lane >> 3;
    int l8 = lane & 7;
    int n = wid * 4 + quad;
    if (wid * 4 >= N) return;
    bool nvalid = (n < N);
    int nn = nvalid ? n : (N - 1);

    float ald = __ldg(&g_ald2[nn]);
    int start = g_off[nn];
    int deg = g_deg[nn];
    int end = start + deg;

    int nb = (deg + 7) >> 3;
    { int t = __shfl_xor_sync(0xffffffffu, nb, 8);  nb = nb > t ? nb : t; }
    { int t = __shfl_xor_sync(0xffffffffu, nb, 16); nb = nb > t ? nb : t; }

    int s = 0; float w;
    {
        int idx = start + l8;
        bool v = nvalid && idx < end;
        float al = 0.f;
        if (v) { s = __ldg(&g_esrc[idx]); al = __ldg(&g_als2[s]); }
        w = v ? __expf(leaky(al + ald)) : 0.f;
    }

    float2 a0 = make_float2(0.f,0.f), a1 = make_float2(0.f,0.f);
    float2 a2 = make_float2(0.f,0.f), a3 = make_float2(0.f,0.f);
    float den = 0.f;
    const __half2* h2p = reinterpret_cast<const __half2*>(g_h2h);
    for (int b = 0; b < nb; b++) {
        int idx2 = start + (b + 1) * 8 + l8;
        bool v2 = nvalid && idx2 < end;
        int s2 = 0; float al2 = 0.f;
        if (v2) { s2 = __ldg(&g_esrc[idx2]); al2 = __ldg(&g_als2[s2]); }

        den += w;
#pragma unroll
        for (int j = 0; j < 8; j += 4) {
            int   s0 = __shfl_sync(0xffffffffu, s, j,     8);
            int   s1 = __shfl_sync(0xffffffffu, s, j + 1, 8);
            int   s2b= __shfl_sync(0xffffffffu, s, j + 2, 8);
            int   s3 = __shfl_sync(0xffffffffu, s, j + 3, 8);
            float w0 = __shfl_sync(0xffffffffu, w, j,     8);
            float w1 = __shfl_sync(0xffffffffu, w, j + 1, 8);
            float w2 = __shfl_sync(0xffffffffu, w, j + 2, 8);
            float w3 = __shfl_sync(0xffffffffu, w, j + 3, 8);
            float2 f0 = __half22float2(__ldg(&h2p[s0 * 8 + l8]));
            float2 f1 = __half22float2(__ldg(&h2p[s1 * 8 + l8]));
            float2 f2 = __half22float2(__ldg(&h2p[s2b* 8 + l8]));
            float2 f3 = __half22float2(__ldg(&h2p[s3 * 8 + l8]));
            a0.x = fmaf(w0, f0.x, a0.x); a0.y = fmaf(w0, f0.y, a0.y);
            a1.x = fmaf(w1, f1.x, a1.x); a1.y = fmaf(w1, f1.y, a1.y);
            a2.x = fmaf(w2, f2.x, a2.x); a2.y = fmaf(w2, f2.y, a2.y);
            a3.x = fmaf(w3, f3.x, a3.x); a3.y = fmaf(w3, f3.y, a3.y);
        }
        s = s2;
        w = v2 ? __expf(leaky(al2 + ald)) : 0.f;
    }
    float2 acc = make_float2((a0.x + a1.x) + (a2.x + a3.x), (a0.y + a1.y) + (a2.y + a3.y));
#pragma unroll
    for (int o = 4; o; o >>= 1) den += __shfl_xor_sync(0xffffffffu, den, o, 8);

    float wself = __expf(leaky(__ldg(&g_als2[nn]) + ald));
    den += wself;
    float2 hs = __half22float2(__ldg(&h2p[nn * 8 + l8]));
    acc.x = fmaf(wself, hs.x, acc.x);
    acc.y = fmaf(wself, hs.y, acc.y);

    float inv = 1.0f / (den + 1e-16f);
    if (nvalid) {
        float2 bv = __ldg(&reinterpret_cast<const float2*>(b2)[l8]);
        float2 r;
        r.x = fmaf(acc.x, inv, bv.x);
        r.y = fmaf(acc.y, inv, bv.y);
        reinterpret_cast<float2*>(&out[n * 16])[l8] = r;
    }
}

// ===========================================================================
extern "C" void kernel_launch(void* const* d_in, const int* in_sizes, int n_in,
                              void* d_out, int out_size)
{
    const float* x   = (const float*)d_in[0];
    const int*   ei  = (const int*)  d_in[1];
    const float* W1  = (const float*)d_in[3];
    const float* as1 = (const float*)d_in[4];
    const float* ad1 = (const float*)d_in[5];
    const float* b1  = (const float*)d_in[6];
    const float* W2  = (const float*)d_in[7];
    const float* as2 = (const float*)d_in[8];
    const float* ad2 = (const float*)d_in[9];
    const float* b2  = (const float*)d_in[10];

    int N = in_sizes[0] / 128;
    int E = in_sizes[1] / 2;
    const int* src = ei;
    const int* dst = ei + E;

    void* p_deg = nullptr; cudaGetSymbolAddress(&p_deg, g_deg);
    void* p_cnt = nullptr; cudaGetSymbolAddress(&p_cnt, g_cnt);
    cudaMemsetAsync(p_deg, 0, (size_t)N * sizeof(int));
    cudaMemsetAsync(p_cnt, 0, sizeof(int));

    int nblkN = (N + 255) / 256;
    int nblkE4 = (E / 4 + 256) / 256;
    int nscan = (N + SCAN_B - 1) / SCAN_B;

    // fused hist (rank-capturing) + node1
    hist_node1_kernel<<<nblkE4 + nblkN, 256>>>(dst, E, x, W1, as1, ad1, N, nblkE4);

    scan1_kernel<<<nscan, SCAN_B>>>(N, nscan);
    scan3_kernel<<<nblkN, 256>>>(N);
    permute_kernel<<<nblkE4, 256>>>(src, dst, E);

    int nwarp1 = (((N + 1) / 2) * 32 + 255) / 256;
    agg1_kernel<<<nwarp1, 256>>>(b1, N);

    node2_kernel<<<nblkN, 256>>>(W2, as2, ad2, N);
    int nwarp2 = (((N + 3) / 4) * 32 + 255) / 256;
    agg2_kernel<<<nwarp2, 256>>>(b2, (float*)d_out, N);
}